// round 13
// baseline (speedup 1.0000x reference)
#include <cuda_runtime.h>
#include <cuda_bf16.h>
#include <math.h>
#include <stdint.h>
#include <string.h>

// ---------------- problem constants ----------------
#define Bsz   8
#define Tsz   1024
#define Dsz   1024
#define Nsz   256
#define Lsz   768
#define Hsz   16
#define HDsz  64
#define TEsz  2048
#define D2sz  2048
#define EPSv  1e-5f

// ---------------- scratch (device globals; allocation-free) ----------------
__device__ __align__(256) __nv_bfloat16 g_xn_bf [Bsz * Tsz * Dsz];
__device__ __align__(256) __nv_bfloat16 g_xfn_bf[Bsz * Nsz * Lsz];
__device__ __align__(256) __nv_bfloat16 g_q_bf  [Bsz * Tsz * Dsz];
__device__ __align__(256) __nv_bfloat16 g_k_bf  [Bsz * Nsz * Dsz];
__device__ __align__(256) __nv_bfloat16 g_v_bf  [Bsz * Nsz * Dsz];
__device__ __align__(256) __nv_bfloat16 g_y_bf  [Bsz * Tsz * Dsz];
__device__ __align__(256) __nv_bfloat16 g_h_bf  [Bsz * Tsz * Dsz];
__device__ __align__(256) __nv_bfloat16 g_wqt   [Dsz * Dsz];
__device__ __align__(256) __nv_bfloat16 g_wkt   [Dsz * Lsz];
__device__ __align__(256) __nv_bfloat16 g_wvt   [Dsz * Lsz];
__device__ __align__(256) __nv_bfloat16 g_woutt [Dsz * Dsz];
__device__ __align__(256) float         g_embo  [Bsz * D2sz];
__device__ __align__(256) float         g_embp  [16 * Bsz * D2sz];

// ---------------- helpers ----------------
__device__ __forceinline__ uint32_t smem_u32(const void* p) {
    uint32_t a;
    asm("{ .reg .u64 t; cvta.to.shared.u64 t, %1; cvt.u32.u64 %0, t; }" : "=r"(a) : "l"(p));
    return a;
}
#define CPA16(dst, src) \
    asm volatile("cp.async.cg.shared.global [%0], [%1], 16;" :: "r"(dst), "l"(src))
#define CPCOMMIT() asm volatile("cp.async.commit_group;")
#define CPWAIT1()  asm volatile("cp.async.wait_group 1;")
#define CPWAIT0()  asm volatile("cp.async.wait_group 0;")

__device__ __forceinline__ void mma16816(float* c, const uint32_t* a, const uint32_t* b) {
    asm volatile(
        "mma.sync.aligned.m16n8k16.row.col.f32.bf16.bf16.f32 "
        "{%0,%1,%2,%3}, {%4,%5,%6,%7}, {%8,%9}, {%0,%1,%2,%3};\n"
        : "+f"(c[0]), "+f"(c[1]), "+f"(c[2]), "+f"(c[3])
        : "r"(a[0]), "r"(a[1]), "r"(a[2]), "r"(a[3]), "r"(b[0]), "r"(b[1]));
}

// ================ 3-stage cp.async-pipelined bf16 TN GEMM ================
// C[m,n] = sum_k A[m,k] * B[n,k]  (+bias[n]) (+addsrc[m,n]); operands k-contig.
// BM=128, BK=32, 3-stage ring, 8 warps as 2x4 (warp tile 64 x BN/4).
// BN=256 instantiation uses 64x64 warp tiles (1 CTA/SM, ~200 regs).
template<int BN, bool HAS_BIAS, bool HAS_ADD, bool OUT_BF16>
__global__ void __launch_bounds__(256, (BN == 128 ? 2 : 1))
mma_gemm3(int K,
          const __nv_bfloat16* __restrict__ A, int lda, long long sAb, long long sAh,
          const __nv_bfloat16* __restrict__ Bm, int ldb, long long sBb, long long sBh,
          void* __restrict__ Cv, int ldc, long long sCb, long long sCh,
          const float* __restrict__ bias,
          const float* __restrict__ addsrc, int ldadd,
          int Hdiv) {
    constexpr int BM = 128, LDK = 40;
    constexpr int WN = BN / 4;
    constexpr int MFRAG = 4;          // WM=64 (2 warp-rows)
    constexpr int NFRAG = WN / 8;
    constexpr int ASTAGE = BM * 80;   // bytes per A stage
    constexpr int BSTAGE = BN * 80;

    extern __shared__ __align__(16) char sm[];
    __nv_bfloat16* AsBase = reinterpret_cast<__nv_bfloat16*>(sm);
    __nv_bfloat16* BsBase = reinterpret_cast<__nv_bfloat16*>(sm + 3 * ASTAGE);

    int z  = blockIdx.z;
    int zb = z / Hdiv, zh = z % Hdiv;
    A  += (size_t)zb * sAb + (size_t)zh * sAh;
    Bm += (size_t)zb * sBb + (size_t)zh * sBh;
    size_t coff = (size_t)zb * sCb + (size_t)zh * sCh;
    const int bm = blockIdx.y * BM;
    const int bn = blockIdx.x * BN;

    const int tid = threadIdx.x, warp = tid >> 5, lane = tid & 31;
    const int wm = (warp >> 2) * 64;
    const int wn = (warp & 3) * WN;
    const int rg = lane >> 2, cg = (lane & 3) * 2;

    const uint32_t AsA = smem_u32(AsBase), BsA = smem_u32(BsBase);

    float acc[MFRAG][NFRAG][4];
#pragma unroll
    for (int i = 0; i < MFRAG; i++)
#pragma unroll
        for (int j = 0; j < NFRAG; j++)
#pragma unroll
            for (int r = 0; r < 4; r++) acc[i][j][r] = 0.f;

    const int KT = K >> 5;

    auto loadt = [&](int kt, int st) {
        const __nv_bfloat16* Ak = A + kt * 32;
#pragma unroll
        for (int i = tid; i < BM * 4; i += 256) {
            int row = i >> 2, part = i & 3;
            CPA16(AsA + (uint32_t)(st * ASTAGE + row * 80 + part * 16),
                  Ak + (size_t)(bm + row) * lda + part * 8);
        }
        const __nv_bfloat16* Bk = Bm + kt * 32;
#pragma unroll
        for (int i = tid; i < BN * 4; i += 256) {
            int row = i >> 2, part = i & 3;
            CPA16(BsA + (uint32_t)(st * BSTAGE + row * 80 + part * 16),
                  Bk + (size_t)(bn + row) * ldb + part * 8);
        }
        CPCOMMIT();
    };

    loadt(0, 0);
    loadt(1, 1);
    int st = 0;
    for (int kt = 0; kt < KT; kt++) {
        if (kt + 1 < KT) CPWAIT1(); else CPWAIT0();
        __syncthreads();
        // safe: buffer (kt+2)%3 == (kt-1)%3 was last read before this barrier
        if (kt + 2 < KT) loadt(kt + 2, (kt + 2) % 3);
        const __nv_bfloat16* Ab = AsBase + st * (ASTAGE / 2);
        const __nv_bfloat16* Bb = BsBase + st * (BSTAGE / 2);
#pragma unroll
        for (int ks = 0; ks < 2; ks++) {
            int kb = ks * 16 + cg;
            uint32_t af[MFRAG][4], bf[NFRAG][2];
#pragma unroll
            for (int mf = 0; mf < MFRAG; mf++) {
                const __nv_bfloat16* p = &Ab[(wm + mf * 16 + rg) * LDK + kb];
                af[mf][0] = *reinterpret_cast<const uint32_t*>(p);
                af[mf][1] = *reinterpret_cast<const uint32_t*>(p + 8 * LDK);
                af[mf][2] = *reinterpret_cast<const uint32_t*>(p + 8);
                af[mf][3] = *reinterpret_cast<const uint32_t*>(p + 8 * LDK + 8);
            }
#pragma unroll
            for (int nf = 0; nf < NFRAG; nf++) {
                const __nv_bfloat16* p = &Bb[(wn + nf * 8 + rg) * LDK + kb];
                bf[nf][0] = *reinterpret_cast<const uint32_t*>(p);
                bf[nf][1] = *reinterpret_cast<const uint32_t*>(p + 8);
            }
#pragma unroll
            for (int mf = 0; mf < MFRAG; mf++)
#pragma unroll
                for (int nf = 0; nf < NFRAG; nf++)
                    mma16816(acc[mf][nf], af[mf], bf[nf]);
        }
        st = (st + 1 == 3) ? 0 : st + 1;
    }

    // ---- epilogue ----
#pragma unroll
    for (int mf = 0; mf < MFRAG; mf++) {
#pragma unroll
        for (int nf = 0; nf < NFRAG; nf++) {
            int n0 = bn + wn + nf * 8 + cg;
#pragma unroll
            for (int hrow = 0; hrow < 2; hrow++) {
                int m = bm + wm + mf * 16 + rg + hrow * 8;
                float v0 = acc[mf][nf][hrow * 2 + 0];
                float v1 = acc[mf][nf][hrow * 2 + 1];
                if (HAS_BIAS) { v0 += bias[n0]; v1 += bias[n0 + 1]; }
                if (HAS_ADD) {
                    float2 a2 = *reinterpret_cast<const float2*>(
                        addsrc + coff + (size_t)m * ldadd + n0);
                    v0 += a2.x; v1 += a2.y;
                }
                if (OUT_BF16) {
                    __nv_bfloat162 o = __floats2bfloat162_rn(v0, v1);
                    *reinterpret_cast<__nv_bfloat162*>(
                        (__nv_bfloat16*)Cv + coff + (size_t)m * ldc + n0) = o;
                } else {
                    float2 o; o.x = v0; o.y = v1;
                    *reinterpret_cast<float2*>(
                        (float*)Cv + coff + (size_t)m * ldc + n0) = o;
                }
            }
        }
    }
}

// ================ fully fused attention: scores + softmax + P@V ================
// Per (b,h, 128-row t-tile): S = q(128,64) @ k(256,64)^T /8; P = softmax_n(S);
// y(128,64) = P @ v(256,64), y written bf16. P lives in smem only.
#define LDQ 72
#define LDP 264
#define SM_ATT (67584 + 36864)

__global__ void __launch_bounds__(256, 1)
fused_attn_kernel(const __nv_bfloat16* __restrict__ qp,
                  const __nv_bfloat16* __restrict__ kp,
                  const __nv_bfloat16* __restrict__ vp,
                  __nv_bfloat16* __restrict__ yp) {
    extern __shared__ __align__(16) char sm[];
    __nv_bfloat16* Qs = reinterpret_cast<__nv_bfloat16*>(sm);            // 128 x LDQ
    __nv_bfloat16* Ks = reinterpret_cast<__nv_bfloat16*>(sm + 18432);    // 256 x LDQ
    __nv_bfloat16* Ps = reinterpret_cast<__nv_bfloat16*>(sm);            // 128 x LDP (overwrites Q/K)
    __nv_bfloat16* Vs = reinterpret_cast<__nv_bfloat16*>(sm + 67584);    // 256 x LDQ
    __shared__ float sred[2][64][4];

    const int z  = blockIdx.z;            // b*16 + h
    const int zb = z >> 4, zh = z & 15;
    const __nv_bfloat16* Aq = qp + (size_t)zb * Tsz * Dsz + zh * HDsz;
    const __nv_bfloat16* Bk = kp + (size_t)zb * Nsz * Dsz + zh * HDsz;
    const __nv_bfloat16* Vv = vp + (size_t)zb * Nsz * Dsz + zh * HDsz;
    __nv_bfloat16* Y = yp + (size_t)zb * Tsz * Dsz + zh * HDsz;
    const int bm = blockIdx.y * 128;

    const int tid = threadIdx.x, warp = tid >> 5, lane = tid & 31;
    const int wr = warp >> 2, wc = warp & 3;
    const int wm = wr * 64, wn = wc * 64;
    const int rg = lane >> 2, cg = (lane & 3) * 2;

    // ---- load Q (128x64), K (256x64), V (256x64) tiles ----
#pragma unroll
    for (int i = tid; i < 128 * 8; i += 256) {
        int row = i >> 3, part = i & 7;
        uint4 t = *reinterpret_cast<const uint4*>(Aq + (size_t)(bm + row) * Dsz + part * 8);
        *reinterpret_cast<uint4*>(&Qs[row * LDQ + part * 8]) = t;
    }
#pragma unroll
    for (int i = tid; i < 256 * 8; i += 256) {
        int row = i >> 3, part = i & 7;
        uint4 t = *reinterpret_cast<const uint4*>(Bk + (size_t)row * Dsz + part * 8);
        *reinterpret_cast<uint4*>(&Ks[row * LDQ + part * 8]) = t;
    }
#pragma unroll
    for (int i = tid; i < 256 * 8; i += 256) {
        int row = i >> 3, part = i & 7;
        uint4 t = *reinterpret_cast<const uint4*>(Vv + (size_t)row * Dsz + part * 8);
        *reinterpret_cast<uint4*>(&Vs[row * LDQ + part * 8]) = t;
    }
    __syncthreads();

    // ---- phase 1: scores S(128,256) = Q @ K^T, warp tile 64x64 ----
    float acc[4][8][4];
#pragma unroll
    for (int i = 0; i < 4; i++)
#pragma unroll
        for (int j = 0; j < 8; j++)
#pragma unroll
            for (int r = 0; r < 4; r++) acc[i][j][r] = 0.f;

#pragma unroll
    for (int ks = 0; ks < 4; ks++) {
        int kb = ks * 16 + cg;
        uint32_t af[4][4], bf[8][2];
#pragma unroll
        for (int mf = 0; mf < 4; mf++) {
            const __nv_bfloat16* p = &Qs[(wm + mf * 16 + rg) * LDQ + kb];
            af[mf][0] = *reinterpret_cast<const uint32_t*>(p);
            af[mf][1] = *reinterpret_cast<const uint32_t*>(p + 8 * LDQ);
            af[mf][2] = *reinterpret_cast<const uint32_t*>(p + 8);
            af[mf][3] = *reinterpret_cast<const uint32_t*>(p + 8 * LDQ + 8);
        }
#pragma unroll
        for (int nf = 0; nf < 8; nf++) {
            const __nv_bfloat16* p = &Ks[(wn + nf * 8 + rg) * LDQ + kb];
            bf[nf][0] = *reinterpret_cast<const uint32_t*>(p);
            bf[nf][1] = *reinterpret_cast<const uint32_t*>(p + 8);
        }
#pragma unroll
        for (int mf = 0; mf < 4; mf++)
#pragma unroll
            for (int nf = 0; nf < 8; nf++)
                mma16816(acc[mf][nf], af[mf], bf[nf]);
    }

    // ---- softmax over n (rows split across 4 warp-cols), scale 1/8 ----
#pragma unroll
    for (int mf = 0; mf < 4; mf++)
#pragma unroll
        for (int nf = 0; nf < 8; nf++)
#pragma unroll
            for (int r = 0; r < 4; r++) acc[mf][nf][r] *= 0.125f;

    float rmax[4][2];
#pragma unroll
    for (int mf = 0; mf < 4; mf++)
#pragma unroll
        for (int hrow = 0; hrow < 2; hrow++) {
            float m = -1e30f;
#pragma unroll
            for (int nf = 0; nf < 8; nf++)
                m = fmaxf(m, fmaxf(acc[mf][nf][hrow * 2], acc[mf][nf][hrow * 2 + 1]));
            m = fmaxf(m, __shfl_xor_sync(0xffffffffu, m, 1));
            m = fmaxf(m, __shfl_xor_sync(0xffffffffu, m, 2));
            if ((lane & 3) == 0) sred[wr][mf * 16 + rg + hrow * 8][wc] = m;
        }
    __syncthreads();
#pragma unroll
    for (int mf = 0; mf < 4; mf++)
#pragma unroll
        for (int hrow = 0; hrow < 2; hrow++) {
            int r = mf * 16 + rg + hrow * 8;
            rmax[mf][hrow] = fmaxf(fmaxf(sred[wr][r][0], sred[wr][r][1]),
                                   fmaxf(sred[wr][r][2], sred[wr][r][3]));
        }
    __syncthreads();
    float rsum[4][2];
#pragma unroll
    for (int mf = 0; mf < 4; mf++)
#pragma unroll
        for (int hrow = 0; hrow < 2; hrow++) {
            float s = 0.f;
#pragma unroll
            for (int nf = 0; nf < 8; nf++) {
                float e0 = __expf(acc[mf][nf][hrow * 2]     - rmax[mf][hrow]);
                float e1 = __expf(acc[mf][nf][hrow * 2 + 1] - rmax[mf][hrow]);
                acc[mf][nf][hrow * 2] = e0; acc[mf][nf][hrow * 2 + 1] = e1;
                s += e0 + e1;
            }
            s += __shfl_xor_sync(0xffffffffu, s, 1);
            s += __shfl_xor_sync(0xffffffffu, s, 2);
            if ((lane & 3) == 0) sred[wr][mf * 16 + rg + hrow * 8][wc] = s;
        }
    __syncthreads();
#pragma unroll
    for (int mf = 0; mf < 4; mf++)
#pragma unroll
        for (int hrow = 0; hrow < 2; hrow++) {
            int r = mf * 16 + rg + hrow * 8;
            float tot = sred[wr][r][0] + sred[wr][r][1] + sred[wr][r][2] + sred[wr][r][3];
            rsum[mf][hrow] = 1.f / tot;
        }
    __syncthreads();   // all Q/K reads done chip-wide before P overwrites them

    // ---- phase 2: store P (bf16) into smem (overwrites Q/K region) ----
#pragma unroll
    for (int mf = 0; mf < 4; mf++)
#pragma unroll
        for (int hrow = 0; hrow < 2; hrow++) {
            int m = wm + mf * 16 + rg + hrow * 8;
            float inv = rsum[mf][hrow];
#pragma unroll
            for (int nf = 0; nf < 8; nf++) {
                __nv_bfloat162 o = __floats2bfloat162_rn(
                    acc[mf][nf][hrow * 2] * inv, acc[mf][nf][hrow * 2 + 1] * inv);
                *reinterpret_cast<__nv_bfloat162*>(&Ps[m * LDP + wn + nf * 8 + cg]) = o;
            }
        }
    __syncthreads();

    // ---- phase 3: y(128,64) = P(128,256) @ V(256,64), warp tile 64x16 ----
    {
        const int wnd = wc * 16;       // output d-columns for this warp
        float acc2[4][2][4];
#pragma unroll
        for (int i = 0; i < 4; i++)
#pragma unroll
            for (int j = 0; j < 2; j++)
#pragma unroll
                for (int r = 0; r < 4; r++) acc2[i][j][r] = 0.f;

#pragma unroll
        for (int ks = 0; ks < 16; ks++) {
            int kb = ks * 16;
            uint32_t af[4][4], bf[2][2];
#pragma unroll
            for (int mf = 0; mf < 4; mf++) {
                const __nv_bfloat16* p = &Ps[(wm + mf * 16 + rg) * LDP + kb + cg];
                af[mf][0] = *reinterpret_cast<const uint32_t*>(p);
                af[mf][1] = *reinterpret_cast<const uint32_t*>(p + 8 * LDP);
                af[mf][2] = *reinterpret_cast<const uint32_t*>(p + 8);
                af[mf][3] = *reinterpret_cast<const uint32_t*>(p + 8 * LDP + 8);
            }
#pragma unroll
            for (int nf = 0; nf < 2; nf++) {
                int dcol = wnd + nf * 8 + rg;
                int kk = kb + cg;
                uint32_t l0 = *reinterpret_cast<const uint16_t*>(&Vs[kk * LDQ + dcol]);
                uint32_t h0 = *reinterpret_cast<const uint16_t*>(&Vs[(kk + 1) * LDQ + dcol]);
                uint32_t l1 = *reinterpret_cast<const uint16_t*>(&Vs[(kk + 8) * LDQ + dcol]);
                uint32_t h1 = *reinterpret_cast<const uint16_t*>(&Vs[(kk + 9) * LDQ + dcol]);
                bf[nf][0] = l0 | (h0 << 16);
                bf[nf][1] = l1 | (h1 << 16);
            }
#pragma unroll
            for (int mf = 0; mf < 4; mf++)
#pragma unroll
                for (int nf = 0; nf < 2; nf++)
                    mma16816(acc2[mf][nf], af[mf], bf[nf]);
        }

        // ---- write y bf16 ----
#pragma unroll
        for (int mf = 0; mf < 4; mf++)
#pragma unroll
            for (int nf = 0; nf < 2; nf++) {
                int d0 = wnd + nf * 8 + cg;
#pragma unroll
                for (int hrow = 0; hrow < 2; hrow++) {
                    int m = bm + wm + mf * 16 + rg + hrow * 8;
                    __nv_bfloat162 o = __floats2bfloat162_rn(
                        acc2[mf][nf][hrow * 2 + 0], acc2[mf][nf][hrow * 2 + 1]);
                    *reinterpret_cast<__nv_bfloat162*>(&Y[(size_t)m * Dsz + d0]) = o;
                }
            }
    }
}

// ---------------- LayerNorm over last dim -> bf16 ----------------
__global__ void ln_bf16_kernel(const float* __restrict__ in,
                               const float* __restrict__ g,
                               const float* __restrict__ b,
                               __nv_bfloat16* __restrict__ out, int C) {
    int row = blockIdx.x;
    const float* ip = in + (size_t)row * C;
    __nv_bfloat16* op = out + (size_t)row * C;
    int tid = threadIdx.x;
    float v[4];
    float s = 0.f, ss = 0.f;
#pragma unroll
    for (int i = 0; i < 4; i++) {
        int c = tid + i * 256;
        float x = (c < C) ? ip[c] : 0.f;
        v[i] = x; s += x; ss += x * x;
    }
    __shared__ float rs[256], rq[256];
    rs[tid] = s; rq[tid] = ss;
    __syncthreads();
    for (int off = 128; off > 0; off >>= 1) {
        if (tid < off) { rs[tid] += rs[tid + off]; rq[tid] += rq[tid + off]; }
        __syncthreads();
    }
    float mean = rs[0] / (float)C;
    float var  = rq[0] / (float)C - mean * mean;
    float inv  = rsqrtf(var + EPSv);
#pragma unroll
    for (int i = 0; i < 4; i++) {
        int c = tid + i * 256;
        if (c < C) op[c] = __float2bfloat16_rn((v[i] - mean) * inv * g[c] + b[c]);
    }
}

// ---------------- LN + modulate + SiLU: bf16 y in -> bf16 h out ----------------
__global__ void styl_kernel(const __nv_bfloat16* __restrict__ y,
                            const float* __restrict__ g,
                            const float* __restrict__ b,
                            const float* __restrict__ embout,
                            __nv_bfloat16* __restrict__ out) {
    int row = blockIdx.x;
    int batch = row / Tsz;
    const __nv_bfloat16* ip = y + (size_t)row * Dsz;
    __nv_bfloat16* op = out + (size_t)row * Dsz;
    const float* sc = embout + (size_t)batch * D2sz;
    const float* sh = embout + (size_t)batch * D2sz + Dsz;
    int tid = threadIdx.x;
    float v[4];
    float s = 0.f, ss = 0.f;
    // vectorized bf16x2 load: thread handles 2 pairs spread across the row
#pragma unroll
    for (int i = 0; i < 2; i++) {
        int c2 = tid + i * 256;              // pair index 0..511
        __nv_bfloat162 h2 = *reinterpret_cast<const __nv_bfloat162*>(ip + c2 * 2);
        float x0 = __bfloat162float(h2.x), x1 = __bfloat162float(h2.y);
        v[i * 2] = x0; v[i * 2 + 1] = x1;
        s += x0 + x1; ss += x0 * x0 + x1 * x1;
    }
    __shared__ float rs[256], rq[256];
    rs[tid] = s; rq[tid] = ss;
    __syncthreads();
    for (int off = 128; off > 0; off >>= 1) {
        if (tid < off) { rs[tid] += rs[tid + off]; rq[tid] += rq[tid + off]; }
        __syncthreads();
    }
    float mean = rs[0] / (float)Dsz;
    float var  = rq[0] / (float)Dsz - mean * mean;
    float inv  = rsqrtf(var + EPSv);
#pragma unroll
    for (int i = 0; i < 2; i++) {
        int c2 = tid + i * 256;
        float o2[2];
#pragma unroll
        for (int j = 0; j < 2; j++) {
            int c = c2 * 2 + j;
            float h = (v[i * 2 + j] - mean) * inv * g[c] + b[c];
            h = h * (1.f + sc[c]) + sh[c];
            o2[j] = h / (1.f + expf(-h));
        }
        *reinterpret_cast<__nv_bfloat162*>(op + c2 * 2) = __floats2bfloat162_rn(o2[0], o2[1]);
    }
}

// ---------------- fused weight convert+transpose (all 4 weights, 1 launch) ----------------
__global__ void transconv4_kernel(const float* __restrict__ Wq,  __nv_bfloat16* __restrict__ wqt,
                                  const float* __restrict__ Wo,  __nv_bfloat16* __restrict__ wot,
                                  const float* __restrict__ Wk,  __nv_bfloat16* __restrict__ wkt,
                                  const float* __restrict__ Wv,  __nv_bfloat16* __restrict__ wvt) {
    __shared__ float tile[32][33];
    int zid = blockIdx.z;
    const float* in; __nv_bfloat16* out; int R;
    if (zid == 0)      { in = Wq; out = wqt; R = 1024; }
    else if (zid == 1) { in = Wo; out = wot; R = 1024; }
    else if (zid == 2) { in = Wk; out = wkt; R = 768; }
    else               { in = Wv; out = wvt; R = 768; }
    int c0 = blockIdx.x * 32, r0 = blockIdx.y * 32;
    if (r0 >= R) return;
    int tx = threadIdx.x, ty = threadIdx.y;
#pragma unroll
    for (int i = 0; i < 32; i += 8)
        tile[ty + i][tx] = in[(size_t)(r0 + ty + i) * Dsz + c0 + tx];
    __syncthreads();
#pragma unroll
    for (int i = 0; i < 32; i += 8)
        out[(size_t)(c0 + ty + i) * R + r0 + tx] = __float2bfloat16_rn(tile[tx][ty + i]);
}

// ---------------- emb GEMM split-K (16 splits, silu fused, full-unroll MLP) ----------------
__global__ void embgemm_part(const float* __restrict__ emb,
                             const float* __restrict__ W,
                             float* __restrict__ part) {
    __shared__ float se[8][128];
    int tid = threadIdx.x;
    int kbase = blockIdx.y * 128;
#pragma unroll
    for (int i = tid; i < 8 * 128; i += 256) {
        int r = i >> 7, c = i & 127;
        float e = emb[(size_t)r * TEsz + kbase + c];
        se[r][c] = e / (1.f + expf(-e));
    }
    __syncthreads();
    int lane = tid & 31, ks = tid >> 5;
    int col = blockIdx.x * 32 + lane;
    float acc[8] = {0,0,0,0,0,0,0,0};
    float wv[16];
#pragma unroll
    for (int j = 0; j < 16; j++)           // 16 independent LDGs (MLP)
        wv[j] = W[(size_t)(kbase + ks * 16 + j) * D2sz + col];
#pragma unroll
    for (int j = 0; j < 16; j++) {
        int kk = ks * 16 + j;
#pragma unroll
        for (int r = 0; r < 8; r++) acc[r] = fmaf(se[r][kk], wv[j], acc[r]);
    }
    __shared__ float sp[8][8][32];
#pragma unroll
    for (int r = 0; r < 8; r++) sp[ks][r][lane] = acc[r];
    __syncthreads();
    int r = tid >> 5;
    float s = 0.f;
#pragma unroll
    for (int s2 = 0; s2 < 8; s2++) s += sp[s2][r][lane];
    part[((size_t)blockIdx.y * 8 + r) * D2sz + col] = s;
}

__global__ void embgemm_reduce(const float* __restrict__ part,
                               const float* __restrict__ bias,
                               float* __restrict__ out) {
    int i = blockIdx.x * 256 + threadIdx.x;
    int r = i / D2sz, c = i % D2sz;
    float s = bias[c];
#pragma unroll
    for (int p = 0; p < 16; p++) s += part[((size_t)p * 8 + r) * D2sz + c];
    out[i] = s;
}

// ---------------- launch ----------------
extern "C" void kernel_launch(void* const* d_in, const int* in_sizes, int n_in,
                              void* d_out, int out_size) {
    const float* x    = (const float*)d_in[0];
    const float* xf   = (const float*)d_in[1];
    const float* emb  = (const float*)d_in[2];
    const float* ln_g = (const float*)d_in[3];
    const float* ln_b = (const float*)d_in[4];
    const float* cln_g= (const float*)d_in[5];
    const float* cln_b= (const float*)d_in[6];
    const float* Wq   = (const float*)d_in[7];
    const float* bq   = (const float*)d_in[8];
    const float* Wk   = (const float*)d_in[9];
    const float* bk   = (const float*)d_in[10];
    const float* Wv   = (const float*)d_in[11];
    const float* bv   = (const float*)d_in[12];
    const float* sln_g= (const float*)d_in[13];
    const float* sln_b= (const float*)d_in[14];
    const float* Wemb = (const float*)d_in[15];
    const float* bemb = (const float*)d_in[16];
    const float* Wout = (const float*)d_in[17];
    const float* bout = (const float*)d_in[18];
    float* out = (float*)d_out;

    __nv_bfloat16 *xn, *xfn, *q, *k, *v, *ybf, *hbf, *wqt, *wkt, *wvt, *woutt;
    float *embo, *embp;
    cudaGetSymbolAddress((void**)&xn,   g_xn_bf);
    cudaGetSymbolAddress((void**)&xfn,  g_xfn_bf);
    cudaGetSymbolAddress((void**)&q,    g_q_bf);
    cudaGetSymbolAddress((void**)&k,    g_k_bf);
    cudaGetSymbolAddress((void**)&v,    g_v_bf);
    cudaGetSymbolAddress((void**)&ybf,  g_y_bf);
    cudaGetSymbolAddress((void**)&hbf,  g_h_bf);
    cudaGetSymbolAddress((void**)&wqt,  g_wqt);
    cudaGetSymbolAddress((void**)&wkt,  g_wkt);
    cudaGetSymbolAddress((void**)&wvt,  g_wvt);
    cudaGetSymbolAddress((void**)&woutt,g_woutt);
    cudaGetSymbolAddress((void**)&embo, g_embo);
    cudaGetSymbolAddress((void**)&embp, g_embp);

    const int SMG128 = 3 * (128 + 128) * 80;       // 61440 B
    const int SMG256 = 3 * (128 + 256) * 80;       // 92160 B
    cudaFuncSetAttribute(mma_gemm3<128,true,false,true >, cudaFuncAttributeMaxDynamicSharedMemorySize, SMG128);
    cudaFuncSetAttribute(mma_gemm3<256,true,false,true >, cudaFuncAttributeMaxDynamicSharedMemorySize, SMG256);
    cudaFuncSetAttribute(mma_gemm3<256,true,true ,false>, cudaFuncAttributeMaxDynamicSharedMemorySize, SMG256);
    cudaFuncSetAttribute(fused_attn_kernel, cudaFuncAttributeMaxDynamicSharedMemorySize, SM_ATT);

    dim3 tb(32, 8);

    // 1. LayerNorms -> bf16
    ln_bf16_kernel<<<Bsz * Tsz, 256>>>(x,  ln_g,  ln_b,  xn,  Dsz);
    ln_bf16_kernel<<<Bsz * Nsz, 256>>>(xf, cln_g, cln_b, xfn, Lsz);

    // 2. all weight convert+transposes in one launch
    transconv4_kernel<<<dim3(32, 32, 4), tb>>>(Wq, wqt, Wout, woutt, Wk, wkt, Wv, wvt);

    // 3. emb path (silu fused, 16-way split-K)
    embgemm_part<<<dim3(64, 16), 256>>>(emb, Wemb, embp);
    embgemm_reduce<<<64, 256>>>(embp, bemb, embo);

    // 4. projections: q with wide tile; k/v keep BN=128 for occupancy
    mma_gemm3<256,true,false,true><<<dim3(Dsz/256, (Bsz*Tsz)/128, 1), 256, SMG256>>>(
        Dsz, xn, Dsz, 0, 0, wqt, Dsz, 0, 0, q, Dsz, 0, 0, bq, nullptr, 0, 1);
    mma_gemm3<128,true,false,true><<<dim3(Dsz/128, (Bsz*Nsz)/128, 1), 256, SMG128>>>(
        Lsz, xfn, Lsz, 0, 0, wkt, Lsz, 0, 0, k, Dsz, 0, 0, bk, nullptr, 0, 1);
    mma_gemm3<128,true,false,true><<<dim3(Dsz/128, (Bsz*Nsz)/128, 1), 256, SMG128>>>(
        Lsz, xfn, Lsz, 0, 0, wvt, Lsz, 0, 0, v, Dsz, 0, 0, bv, nullptr, 0, 1);

    // 5. fused attention: scores + softmax + P@V, y bf16 out
    fused_attn_kernel<<<dim3(1, Tsz/128, Bsz*Hsz), 256, SM_ATT>>>(q, k, v, ybf);

    // 6. stylization front: hbf = silu(LN(y)*(1+scale)+shift) in bf16
    styl_kernel<<<Bsz * Tsz, 256>>>(ybf, sln_g, sln_b, embo, hbf);

    // 7. out = x + hbf @ Wout + bout  (fp32 out, wide tile)
    mma_gemm3<256,true,true,false><<<dim3(Dsz/256, (Bsz*Tsz)/128, 1), 256, SMG256>>>(
        Dsz, hbf, Dsz, 0, 0, woutt, Dsz, 0, 0,
        out, Dsz, 0, 0, bout, x, Dsz, 1);
}

// round 15
// speedup vs baseline: 1.0758x; 1.0758x over previous
#include <cuda_runtime.h>
#include <cuda_bf16.h>
#include <math.h>
#include <stdint.h>
#include <string.h>

// ---------------- problem constants ----------------
#define Bsz   8
#define Tsz   1024
#define Dsz   1024
#define Nsz   256
#define Lsz   768
#define Hsz   16
#define HDsz  64
#define TEsz  2048
#define D2sz  2048
#define EPSv  1e-5f

// ---------------- scratch (device globals; allocation-free) ----------------
__device__ __align__(256) __nv_bfloat16 g_xn_bf [Bsz * Tsz * Dsz];
__device__ __align__(256) __nv_bfloat16 g_xfn_bf[Bsz * Nsz * Lsz];
__device__ __align__(256) __nv_bfloat16 g_q_bf  [Bsz * Tsz * Dsz];
__device__ __align__(256) __nv_bfloat16 g_k_bf  [Bsz * Nsz * Dsz];
__device__ __align__(256) __nv_bfloat16 g_v_bf  [Bsz * Nsz * Dsz];
__device__ __align__(256) __nv_bfloat16 g_y_bf  [Bsz * Tsz * Dsz];
__device__ __align__(256) __nv_bfloat16 g_h_bf  [Bsz * Tsz * Dsz];
__device__ __align__(256) __nv_bfloat16 g_wqt   [Dsz * Dsz];
__device__ __align__(256) __nv_bfloat16 g_wkt   [Dsz * Lsz];
__device__ __align__(256) __nv_bfloat16 g_wvt   [Dsz * Lsz];
__device__ __align__(256) __nv_bfloat16 g_woutt [Dsz * Dsz];
__device__ __align__(256) float         g_embo  [Bsz * D2sz];
__device__ __align__(256) float         g_embp  [16 * Bsz * D2sz];

// ---------------- helpers ----------------
__device__ __forceinline__ uint32_t smem_u32(const void* p) {
    uint32_t a;
    asm("{ .reg .u64 t; cvta.to.shared.u64 t, %1; cvt.u32.u64 %0, t; }" : "=r"(a) : "l"(p));
    return a;
}
#define CPA16(dst, src) \
    asm volatile("cp.async.cg.shared.global [%0], [%1], 16;" :: "r"(dst), "l"(src))
#define CPCOMMIT() asm volatile("cp.async.commit_group;")
#define CPWAIT1()  asm volatile("cp.async.wait_group 1;")
#define CPWAIT0()  asm volatile("cp.async.wait_group 0;")

#define LDSM4(r0, r1, r2, r3, addr) \
    asm volatile("ldmatrix.sync.aligned.m8n8.x4.shared.b16 {%0,%1,%2,%3}, [%4];" \
                 : "=r"(r0), "=r"(r1), "=r"(r2), "=r"(r3) : "r"(addr))

__device__ __forceinline__ void mma16816(float* c, const uint32_t* a, const uint32_t* b) {
    asm volatile(
        "mma.sync.aligned.m16n8k16.row.col.f32.bf16.bf16.f32 "
        "{%0,%1,%2,%3}, {%4,%5,%6,%7}, {%8,%9}, {%0,%1,%2,%3};\n"
        : "+f"(c[0]), "+f"(c[1]), "+f"(c[2]), "+f"(c[3])
        : "r"(a[0]), "r"(a[1]), "r"(a[2]), "r"(a[3]), "r"(b[0]), "r"(b[1]));
}

// ================ 3-stage cp.async-pipelined bf16 TN GEMM (ldmatrix) ================
// C[m,n] = sum_k A[m,k] * B[n,k]  (+bias[n]) (+addsrc[m,n]); operands k-contig.
// BM=128, BN=128, BK=32, 3-stage ring, 8 warps as 2x4 (warp tile 64x32).
template<bool HAS_BIAS, bool HAS_ADD, bool OUT_BF16>
__global__ void __launch_bounds__(256, 2)
mma_gemm3(int K,
          const __nv_bfloat16* __restrict__ A, int lda, long long sAb, long long sAh,
          const __nv_bfloat16* __restrict__ Bm, int ldb, long long sBb, long long sBh,
          void* __restrict__ Cv, int ldc, long long sCb, long long sCh,
          const float* __restrict__ bias,
          const float* __restrict__ addsrc, int ldadd,
          int Hdiv) {
    constexpr int BM = 128, BN = 128, LDK = 40;
    constexpr int WN = BN / 4;        // 32
    constexpr int MFRAG = 4;          // WM=64
    constexpr int NFRAG = WN / 8;     // 4
    constexpr int ASTAGE = BM * 80;   // bytes per A stage
    constexpr int BSTAGE = BN * 80;

    extern __shared__ __align__(16) char sm[];
    __nv_bfloat16* AsBase = reinterpret_cast<__nv_bfloat16*>(sm);
    __nv_bfloat16* BsBase = reinterpret_cast<__nv_bfloat16*>(sm + 3 * ASTAGE);

    int z  = blockIdx.z;
    int zb = z / Hdiv, zh = z % Hdiv;
    A  += (size_t)zb * sAb + (size_t)zh * sAh;
    Bm += (size_t)zb * sBb + (size_t)zh * sBh;
    size_t coff = (size_t)zb * sCb + (size_t)zh * sCh;
    const int bm = blockIdx.y * BM;
    const int bn = blockIdx.x * BN;

    const int tid = threadIdx.x, warp = tid >> 5, lane = tid & 31;
    const int wm = (warp >> 2) * 64;
    const int wn = (warp & 3) * WN;

    const uint32_t AsA = smem_u32(AsBase), BsA = smem_u32(BsBase);

    // ldmatrix per-lane address components
    // A groups: {r0,c0},{r8,c0},{r0,c8},{r8,c8}
    const int aRow  = wm + ((lane >> 3) & 1) * 8 + (lane & 7);
    const int aColB = (lane >> 4) * 8;
    // B groups: {n0,k0},{n0,k8},{n16-block rows via pair offset}
    const int bRow  = wn + (lane >> 4) * 8 + (lane & 7);
    const int bColB = ((lane >> 3) & 1) * 8;

    float acc[MFRAG][NFRAG][4];
#pragma unroll
    for (int i = 0; i < MFRAG; i++)
#pragma unroll
        for (int j = 0; j < NFRAG; j++)
#pragma unroll
            for (int r = 0; r < 4; r++) acc[i][j][r] = 0.f;

    const int KT = K >> 5;

    auto loadt = [&](int kt, int st) {
        const __nv_bfloat16* Ak = A + kt * 32;
#pragma unroll
        for (int i = tid; i < BM * 4; i += 256) {
            int row = i >> 2, part = i & 3;
            CPA16(AsA + (uint32_t)(st * ASTAGE + row * 80 + part * 16),
                  Ak + (size_t)(bm + row) * lda + part * 8);
        }
        const __nv_bfloat16* Bk = Bm + kt * 32;
#pragma unroll
        for (int i = tid; i < BN * 4; i += 256) {
            int row = i >> 2, part = i & 3;
            CPA16(BsA + (uint32_t)(st * BSTAGE + row * 80 + part * 16),
                  Bk + (size_t)(bn + row) * ldb + part * 8);
        }
        CPCOMMIT();
    };

    loadt(0, 0);
    loadt(1, 1);
    int st = 0;
    for (int kt = 0; kt < KT; kt++) {
        if (kt + 1 < KT) CPWAIT1(); else CPWAIT0();
        __syncthreads();
        if (kt + 2 < KT) loadt(kt + 2, (kt + 2) % 3);
        const uint32_t Abase = AsA + st * ASTAGE;
        const uint32_t Bbase = BsA + st * BSTAGE;
#pragma unroll
        for (int ks = 0; ks < 2; ks++) {
            uint32_t af[MFRAG][4], bf[NFRAG][2];
#pragma unroll
            for (int mf = 0; mf < MFRAG; mf++) {
                uint32_t ad = Abase + (uint32_t)(((aRow + mf * 16) * LDK + ks * 16 + aColB) * 2);
                LDSM4(af[mf][0], af[mf][1], af[mf][2], af[mf][3], ad);
            }
#pragma unroll
            for (int np = 0; np < NFRAG / 2; np++) {
                uint32_t bd = Bbase + (uint32_t)(((bRow + np * 16) * LDK + ks * 16 + bColB) * 2);
                LDSM4(bf[np*2][0], bf[np*2][1], bf[np*2+1][0], bf[np*2+1][1], bd);
            }
#pragma unroll
            for (int mf = 0; mf < MFRAG; mf++)
#pragma unroll
                for (int nf = 0; nf < NFRAG; nf++)
                    mma16816(acc[mf][nf], af[mf], bf[nf]);
        }
        st = (st + 1 == 3) ? 0 : st + 1;
    }

    // ---- epilogue ----
    const int rg = lane >> 2, cg = (lane & 3) * 2;
#pragma unroll
    for (int mf = 0; mf < MFRAG; mf++) {
#pragma unroll
        for (int nf = 0; nf < NFRAG; nf++) {
            int n0 = bn + wn + nf * 8 + cg;
#pragma unroll
            for (int hrow = 0; hrow < 2; hrow++) {
                int m = bm + wm + mf * 16 + rg + hrow * 8;
                float v0 = acc[mf][nf][hrow * 2 + 0];
                float v1 = acc[mf][nf][hrow * 2 + 1];
                if (HAS_BIAS) { v0 += bias[n0]; v1 += bias[n0 + 1]; }
                if (HAS_ADD) {
                    float2 a2 = *reinterpret_cast<const float2*>(
                        addsrc + coff + (size_t)m * ldadd + n0);
                    v0 += a2.x; v1 += a2.y;
                }
                if (OUT_BF16) {
                    __nv_bfloat162 o = __floats2bfloat162_rn(v0, v1);
                    *reinterpret_cast<__nv_bfloat162*>(
                        (__nv_bfloat16*)Cv + coff + (size_t)m * ldc + n0) = o;
                } else {
                    float2 o; o.x = v0; o.y = v1;
                    *reinterpret_cast<float2*>(
                        (float*)Cv + coff + (size_t)m * ldc + n0) = o;
                }
            }
        }
    }
}

// ================ fully fused attention: scores + softmax + P@V ================
#define LDQ 72
#define LDP 264
#define SM_ATT (67584 + 36864)

__global__ void __launch_bounds__(256, 1)
fused_attn_kernel(const __nv_bfloat16* __restrict__ qp,
                  const __nv_bfloat16* __restrict__ kp,
                  const __nv_bfloat16* __restrict__ vp,
                  __nv_bfloat16* __restrict__ yp) {
    extern __shared__ __align__(16) char sm[];
    __nv_bfloat16* Qs = reinterpret_cast<__nv_bfloat16*>(sm);            // 128 x LDQ
    __nv_bfloat16* Ks = reinterpret_cast<__nv_bfloat16*>(sm + 18432);    // 256 x LDQ
    __nv_bfloat16* Ps = reinterpret_cast<__nv_bfloat16*>(sm);            // 128 x LDP
    __nv_bfloat16* Vs = reinterpret_cast<__nv_bfloat16*>(sm + 67584);    // 256 x LDQ
    __shared__ float sred[2][64][4];

    const int z  = blockIdx.z;            // b*16 + h
    const int zb = z >> 4, zh = z & 15;
    const __nv_bfloat16* Aq = qp + (size_t)zb * Tsz * Dsz + zh * HDsz;
    const __nv_bfloat16* Bk = kp + (size_t)zb * Nsz * Dsz + zh * HDsz;
    const __nv_bfloat16* Vv = vp + (size_t)zb * Nsz * Dsz + zh * HDsz;
    __nv_bfloat16* Y = yp + (size_t)zb * Tsz * Dsz + zh * HDsz;
    const int bm = blockIdx.y * 128;

    const int tid = threadIdx.x, warp = tid >> 5, lane = tid & 31;
    const int wr = warp >> 2, wc = warp & 3;
    const int wm = wr * 64, wn = wc * 64;
    const int rg = lane >> 2, cg = (lane & 3) * 2;

    const uint32_t QsU = smem_u32(Qs), KsU = smem_u32(Ks), PsU = smem_u32(Ps);

    const int aRow  = wm + ((lane >> 3) & 1) * 8 + (lane & 7);
    const int aColB = (lane >> 4) * 8;
    const int bRow  = wn + (lane >> 4) * 8 + (lane & 7);
    const int bColB = ((lane >> 3) & 1) * 8;

    // ---- load Q, K, V tiles ----
#pragma unroll
    for (int i = tid; i < 128 * 8; i += 256) {
        int row = i >> 3, part = i & 7;
        uint4 t = *reinterpret_cast<const uint4*>(Aq + (size_t)(bm + row) * Dsz + part * 8);
        *reinterpret_cast<uint4*>(&Qs[row * LDQ + part * 8]) = t;
    }
#pragma unroll
    for (int i = tid; i < 256 * 8; i += 256) {
        int row = i >> 3, part = i & 7;
        uint4 t = *reinterpret_cast<const uint4*>(Bk + (size_t)row * Dsz + part * 8);
        *reinterpret_cast<uint4*>(&Ks[row * LDQ + part * 8]) = t;
    }
#pragma unroll
    for (int i = tid; i < 256 * 8; i += 256) {
        int row = i >> 3, part = i & 7;
        uint4 t = *reinterpret_cast<const uint4*>(Vv + (size_t)row * Dsz + part * 8);
        *reinterpret_cast<uint4*>(&Vs[row * LDQ + part * 8]) = t;
    }
    __syncthreads();

    // ---- phase 1: scores S(128,256) = Q @ K^T (ldmatrix) ----
    float acc[4][8][4];
#pragma unroll
    for (int i = 0; i < 4; i++)
#pragma unroll
        for (int j = 0; j < 8; j++)
#pragma unroll
            for (int r = 0; r < 4; r++) acc[i][j][r] = 0.f;

#pragma unroll
    for (int ks = 0; ks < 4; ks++) {
        uint32_t af[4][4], bf[8][2];
#pragma unroll
        for (int mf = 0; mf < 4; mf++) {
            uint32_t ad = QsU + (uint32_t)(((aRow + mf * 16) * LDQ + ks * 16 + aColB) * 2);
            LDSM4(af[mf][0], af[mf][1], af[mf][2], af[mf][3], ad);
        }
#pragma unroll
        for (int np = 0; np < 4; np++) {
            uint32_t bd = KsU + (uint32_t)(((bRow + np * 16) * LDQ + ks * 16 + bColB) * 2);
            LDSM4(bf[np*2][0], bf[np*2][1], bf[np*2+1][0], bf[np*2+1][1], bd);
        }
#pragma unroll
        for (int mf = 0; mf < 4; mf++)
#pragma unroll
            for (int nf = 0; nf < 8; nf++)
                mma16816(acc[mf][nf], af[mf], bf[nf]);
    }

    // ---- softmax over n (rows split across 4 warp-cols), scale 1/8 ----
#pragma unroll
    for (int mf = 0; mf < 4; mf++)
#pragma unroll
        for (int nf = 0; nf < 8; nf++)
#pragma unroll
            for (int r = 0; r < 4; r++) acc[mf][nf][r] *= 0.125f;

    float rmax[4][2];
#pragma unroll
    for (int mf = 0; mf < 4; mf++)
#pragma unroll
        for (int hrow = 0; hrow < 2; hrow++) {
            float m = -1e30f;
#pragma unroll
            for (int nf = 0; nf < 8; nf++)
                m = fmaxf(m, fmaxf(acc[mf][nf][hrow * 2], acc[mf][nf][hrow * 2 + 1]));
            m = fmaxf(m, __shfl_xor_sync(0xffffffffu, m, 1));
            m = fmaxf(m, __shfl_xor_sync(0xffffffffu, m, 2));
            if ((lane & 3) == 0) sred[wr][mf * 16 + rg + hrow * 8][wc] = m;
        }
    __syncthreads();
#pragma unroll
    for (int mf = 0; mf < 4; mf++)
#pragma unroll
        for (int hrow = 0; hrow < 2; hrow++) {
            int r = mf * 16 + rg + hrow * 8;
            rmax[mf][hrow] = fmaxf(fmaxf(sred[wr][r][0], sred[wr][r][1]),
                                   fmaxf(sred[wr][r][2], sred[wr][r][3]));
        }
    __syncthreads();
    float rsum[4][2];
#pragma unroll
    for (int mf = 0; mf < 4; mf++)
#pragma unroll
        for (int hrow = 0; hrow < 2; hrow++) {
            float s = 0.f;
#pragma unroll
            for (int nf = 0; nf < 8; nf++) {
                float e0 = __expf(acc[mf][nf][hrow * 2]     - rmax[mf][hrow]);
                float e1 = __expf(acc[mf][nf][hrow * 2 + 1] - rmax[mf][hrow]);
                acc[mf][nf][hrow * 2] = e0; acc[mf][nf][hrow * 2 + 1] = e1;
                s += e0 + e1;
            }
            s += __shfl_xor_sync(0xffffffffu, s, 1);
            s += __shfl_xor_sync(0xffffffffu, s, 2);
            if ((lane & 3) == 0) sred[wr][mf * 16 + rg + hrow * 8][wc] = s;
        }
    __syncthreads();
#pragma unroll
    for (int mf = 0; mf < 4; mf++)
#pragma unroll
        for (int hrow = 0; hrow < 2; hrow++) {
            int r = mf * 16 + rg + hrow * 8;
            float tot = sred[wr][r][0] + sred[wr][r][1] + sred[wr][r][2] + sred[wr][r][3];
            rsum[mf][hrow] = 1.f / tot;
        }
    __syncthreads();   // all Q/K reads done before P overwrites them

    // ---- phase 2: store P (bf16) into smem ----
#pragma unroll
    for (int mf = 0; mf < 4; mf++)
#pragma unroll
        for (int hrow = 0; hrow < 2; hrow++) {
            int m = wm + mf * 16 + rg + hrow * 8;
            float inv = rsum[mf][hrow];
#pragma unroll
            for (int nf = 0; nf < 8; nf++) {
                __nv_bfloat162 o = __floats2bfloat162_rn(
                    acc[mf][nf][hrow * 2] * inv, acc[mf][nf][hrow * 2 + 1] * inv);
                *reinterpret_cast<__nv_bfloat162*>(&Ps[m * LDP + wn + nf * 8 + cg]) = o;
            }
        }
    __syncthreads();

    // ---- phase 3: y(128,64) = P(128,256) @ V(256,64), warp tile 64x16 ----
    {
        const int wnd = wc * 16;
        float acc2[4][2][4];
#pragma unroll
        for (int i = 0; i < 4; i++)
#pragma unroll
            for (int j = 0; j < 2; j++)
#pragma unroll
                for (int r = 0; r < 4; r++) acc2[i][j][r] = 0.f;

        const int pRow  = wm + ((lane >> 3) & 1) * 8 + (lane & 7);
#pragma unroll
        for (int ks = 0; ks < 16; ks++) {
            int kb = ks * 16;
            uint32_t af[4][4], bf[2][2];
#pragma unroll
            for (int mf = 0; mf < 4; mf++) {
                uint32_t ad = PsU + (uint32_t)(((pRow + mf * 16) * LDP + kb + aColB) * 2);
                LDSM4(af[mf][0], af[mf][1], af[mf][2], af[mf][3], ad);
            }
#pragma unroll
            for (int nf = 0; nf < 2; nf++) {
                int dcol = wnd + nf * 8 + rg;
                int kk = kb + cg;
                uint32_t l0 = *reinterpret_cast<const uint16_t*>(&Vs[kk * LDQ + dcol]);
                uint32_t h0 = *reinterpret_cast<const uint16_t*>(&Vs[(kk + 1) * LDQ + dcol]);
                uint32_t l1 = *reinterpret_cast<const uint16_t*>(&Vs[(kk + 8) * LDQ + dcol]);
                uint32_t h1 = *reinterpret_cast<const uint16_t*>(&Vs[(kk + 9) * LDQ + dcol]);
                bf[nf][0] = l0 | (h0 << 16);
                bf[nf][1] = l1 | (h1 << 16);
            }
#pragma unroll
            for (int mf = 0; mf < 4; mf++)
#pragma unroll
                for (int nf = 0; nf < 2; nf++)
                    mma16816(acc2[mf][nf], af[mf], bf[nf]);
        }

        // ---- write y bf16 ----
#pragma unroll
        for (int mf = 0; mf < 4; mf++)
#pragma unroll
            for (int nf = 0; nf < 2; nf++) {
                int d0 = wnd + nf * 8 + cg;
#pragma unroll
                for (int hrow = 0; hrow < 2; hrow++) {
                    int m = bm + wm + mf * 16 + rg + hrow * 8;
                    __nv_bfloat162 o = __floats2bfloat162_rn(
                        acc2[mf][nf][hrow * 2 + 0], acc2[mf][nf][hrow * 2 + 1]);
                    *reinterpret_cast<__nv_bfloat162*>(&Y[(size_t)m * Dsz + d0]) = o;
                }
            }
    }
}

// ---------------- LayerNorm over last dim -> bf16 ----------------
__global__ void ln_bf16_kernel(const float* __restrict__ in,
                               const float* __restrict__ g,
                               const float* __restrict__ b,
                               __nv_bfloat16* __restrict__ out, int C) {
    int row = blockIdx.x;
    const float* ip = in + (size_t)row * C;
    __nv_bfloat16* op = out + (size_t)row * C;
    int tid = threadIdx.x;
    float v[4];
    float s = 0.f, ss = 0.f;
#pragma unroll
    for (int i = 0; i < 4; i++) {
        int c = tid + i * 256;
        float x = (c < C) ? ip[c] : 0.f;
        v[i] = x; s += x; ss += x * x;
    }
    __shared__ float rs[256], rq[256];
    rs[tid] = s; rq[tid] = ss;
    __syncthreads();
    for (int off = 128; off > 0; off >>= 1) {
        if (tid < off) { rs[tid] += rs[tid + off]; rq[tid] += rq[tid + off]; }
        __syncthreads();
    }
    float mean = rs[0] / (float)C;
    float var  = rq[0] / (float)C - mean * mean;
    float inv  = rsqrtf(var + EPSv);
#pragma unroll
    for (int i = 0; i < 4; i++) {
        int c = tid + i * 256;
        if (c < C) op[c] = __float2bfloat16_rn((v[i] - mean) * inv * g[c] + b[c]);
    }
}

// ---------------- LN + modulate + SiLU: bf16 y in -> bf16 h out ----------------
__global__ void styl_kernel(const __nv_bfloat16* __restrict__ y,
                            const float* __restrict__ g,
                            const float* __restrict__ b,
                            const float* __restrict__ embout,
                            __nv_bfloat16* __restrict__ out) {
    int row = blockIdx.x;
    int batch = row / Tsz;
    const __nv_bfloat16* ip = y + (size_t)row * Dsz;
    __nv_bfloat16* op = out + (size_t)row * Dsz;
    const float* sc = embout + (size_t)batch * D2sz;
    const float* sh = embout + (size_t)batch * D2sz + Dsz;
    int tid = threadIdx.x;
    float v[4];
    float s = 0.f, ss = 0.f;
#pragma unroll
    for (int i = 0; i < 2; i++) {
        int c2 = tid + i * 256;
        __nv_bfloat162 h2 = *reinterpret_cast<const __nv_bfloat162*>(ip + c2 * 2);
        float x0 = __bfloat162float(h2.x), x1 = __bfloat162float(h2.y);
        v[i * 2] = x0; v[i * 2 + 1] = x1;
        s += x0 + x1; ss += x0 * x0 + x1 * x1;
    }
    __shared__ float rs[256], rq[256];
    rs[tid] = s; rq[tid] = ss;
    __syncthreads();
    for (int off = 128; off > 0; off >>= 1) {
        if (tid < off) { rs[tid] += rs[tid + off]; rq[tid] += rq[tid + off]; }
        __syncthreads();
    }
    float mean = rs[0] / (float)Dsz;
    float var  = rq[0] / (float)Dsz - mean * mean;
    float inv  = rsqrtf(var + EPSv);
#pragma unroll
    for (int i = 0; i < 2; i++) {
        int c2 = tid + i * 256;
        float o2[2];
#pragma unroll
        for (int j = 0; j < 2; j++) {
            int c = c2 * 2 + j;
            float h = (v[i * 2 + j] - mean) * inv * g[c] + b[c];
            h = h * (1.f + sc[c]) + sh[c];
            o2[j] = h / (1.f + expf(-h));
        }
        *reinterpret_cast<__nv_bfloat162*>(op + c2 * 2) = __floats2bfloat162_rn(o2[0], o2[1]);
    }
}

// ---------------- fused weight convert+transpose (all 4 weights, 1 launch) ----------------
__global__ void transconv4_kernel(const float* __restrict__ Wq,  __nv_bfloat16* __restrict__ wqt,
                                  const float* __restrict__ Wo,  __nv_bfloat16* __restrict__ wot,
                                  const float* __restrict__ Wk,  __nv_bfloat16* __restrict__ wkt,
                                  const float* __restrict__ Wv,  __nv_bfloat16* __restrict__ wvt) {
    __shared__ float tile[32][33];
    int zid = blockIdx.z;
    const float* in; __nv_bfloat16* out; int R;
    if (zid == 0)      { in = Wq; out = wqt; R = 1024; }
    else if (zid == 1) { in = Wo; out = wot; R = 1024; }
    else if (zid == 2) { in = Wk; out = wkt; R = 768; }
    else               { in = Wv; out = wvt; R = 768; }
    int c0 = blockIdx.x * 32, r0 = blockIdx.y * 32;
    if (r0 >= R) return;
    int tx = threadIdx.x, ty = threadIdx.y;
#pragma unroll
    for (int i = 0; i < 32; i += 8)
        tile[ty + i][tx] = in[(size_t)(r0 + ty + i) * Dsz + c0 + tx];
    __syncthreads();
#pragma unroll
    for (int i = 0; i < 32; i += 8)
        out[(size_t)(c0 + ty + i) * R + r0 + tx] = __float2bfloat16_rn(tile[tx][ty + i]);
}

// ---------------- emb GEMM split-K (16 splits, silu fused, full-unroll MLP) ----------------
__global__ void embgemm_part(const float* __restrict__ emb,
                             const float* __restrict__ W,
                             float* __restrict__ part) {
    __shared__ float se[8][128];
    int tid = threadIdx.x;
    int kbase = blockIdx.y * 128;
#pragma unroll
    for (int i = tid; i < 8 * 128; i += 256) {
        int r = i >> 7, c = i & 127;
        float e = emb[(size_t)r * TEsz + kbase + c];
        se[r][c] = e / (1.f + expf(-e));
    }
    __syncthreads();
    int lane = tid & 31, ks = tid >> 5;
    int col = blockIdx.x * 32 + lane;
    float acc[8] = {0,0,0,0,0,0,0,0};
    float wv[16];
#pragma unroll
    for (int j = 0; j < 16; j++)
        wv[j] = W[(size_t)(kbase + ks * 16 + j) * D2sz + col];
#pragma unroll
    for (int j = 0; j < 16; j++) {
        int kk = ks * 16 + j;
#pragma unroll
        for (int r = 0; r < 8; r++) acc[r] = fmaf(se[r][kk], wv[j], acc[r]);
    }
    __shared__ float sp[8][8][32];
#pragma unroll
    for (int r = 0; r < 8; r++) sp[ks][r][lane] = acc[r];
    __syncthreads();
    int r = tid >> 5;
    float s = 0.f;
#pragma unroll
    for (int s2 = 0; s2 < 8; s2++) s += sp[s2][r][lane];
    part[((size_t)blockIdx.y * 8 + r) * D2sz + col] = s;
}

__global__ void embgemm_reduce(const float* __restrict__ part,
                               const float* __restrict__ bias,
                               float* __restrict__ out) {
    int i = blockIdx.x * 256 + threadIdx.x;
    int r = i / D2sz, c = i % D2sz;
    float s = bias[c];
#pragma unroll
    for (int p = 0; p < 16; p++) s += part[((size_t)p * 8 + r) * D2sz + c];
    out[i] = s;
}

// ---------------- launch ----------------
extern "C" void kernel_launch(void* const* d_in, const int* in_sizes, int n_in,
                              void* d_out, int out_size) {
    const float* x    = (const float*)d_in[0];
    const float* xf   = (const float*)d_in[1];
    const float* emb  = (const float*)d_in[2];
    const float* ln_g = (const float*)d_in[3];
    const float* ln_b = (const float*)d_in[4];
    const float* cln_g= (const float*)d_in[5];
    const float* cln_b= (const float*)d_in[6];
    const float* Wq   = (const float*)d_in[7];
    const float* bq   = (const float*)d_in[8];
    const float* Wk   = (const float*)d_in[9];
    const float* bk   = (const float*)d_in[10];
    const float* Wv   = (const float*)d_in[11];
    const float* bv   = (const float*)d_in[12];
    const float* sln_g= (const float*)d_in[13];
    const float* sln_b= (const float*)d_in[14];
    const float* Wemb = (const float*)d_in[15];
    const float* bemb = (const float*)d_in[16];
    const float* Wout = (const float*)d_in[17];
    const float* bout = (const float*)d_in[18];
    float* out = (float*)d_out;

    __nv_bfloat16 *xn, *xfn, *q, *k, *v, *ybf, *hbf, *wqt, *wkt, *wvt, *woutt;
    float *embo, *embp;
    cudaGetSymbolAddress((void**)&xn,   g_xn_bf);
    cudaGetSymbolAddress((void**)&xfn,  g_xfn_bf);
    cudaGetSymbolAddress((void**)&q,    g_q_bf);
    cudaGetSymbolAddress((void**)&k,    g_k_bf);
    cudaGetSymbolAddress((void**)&v,    g_v_bf);
    cudaGetSymbolAddress((void**)&ybf,  g_y_bf);
    cudaGetSymbolAddress((void**)&hbf,  g_h_bf);
    cudaGetSymbolAddress((void**)&wqt,  g_wqt);
    cudaGetSymbolAddress((void**)&wkt,  g_wkt);
    cudaGetSymbolAddress((void**)&wvt,  g_wvt);
    cudaGetSymbolAddress((void**)&woutt,g_woutt);
    cudaGetSymbolAddress((void**)&embo, g_embo);
    cudaGetSymbolAddress((void**)&embp, g_embp);

    const int SMG128 = 3 * (128 + 128) * 80;       // 61440 B
    cudaFuncSetAttribute(mma_gemm3<true,false,true >, cudaFuncAttributeMaxDynamicSharedMemorySize, SMG128);
    cudaFuncSetAttribute(mma_gemm3<true,true ,false>, cudaFuncAttributeMaxDynamicSharedMemorySize, SMG128);
    cudaFuncSetAttribute(fused_attn_kernel, cudaFuncAttributeMaxDynamicSharedMemorySize, SM_ATT);

    dim3 tb(32, 8);

    // 1. LayerNorms -> bf16
    ln_bf16_kernel<<<Bsz * Tsz, 256>>>(x,  ln_g,  ln_b,  xn,  Dsz);
    ln_bf16_kernel<<<Bsz * Nsz, 256>>>(xf, cln_g, cln_b, xfn, Lsz);

    // 2. all weight convert+transposes in one launch
    transconv4_kernel<<<dim3(32, 32, 4), tb>>>(Wq, wqt, Wout, woutt, Wk, wkt, Wv, wvt);

    // 3. emb path (silu fused, 16-way split-K)
    embgemm_part<<<dim3(64, 16), 256>>>(emb, Wemb, embp);
    embgemm_reduce<<<64, 256>>>(embp, bemb, embo);

    // 4. projections (BN=128, ldmatrix)
    mma_gemm3<true,false,true><<<dim3(Dsz/128, (Bsz*Tsz)/128, 1), 256, SMG128>>>(
        Dsz, xn, Dsz, 0, 0, wqt, Dsz, 0, 0, q, Dsz, 0, 0, bq, nullptr, 0, 1);
    mma_gemm3<true,false,true><<<dim3(Dsz/128, (Bsz*Nsz)/128, 1), 256, SMG128>>>(
        Lsz, xfn, Lsz, 0, 0, wkt, Lsz, 0, 0, k, Dsz, 0, 0, bk, nullptr, 0, 1);
    mma_gemm3<true,false,true><<<dim3(Dsz/128, (Bsz*Nsz)/128, 1), 256, SMG128>>>(
        Lsz, xfn, Lsz, 0, 0, wvt, Lsz, 0, 0, v, Dsz, 0, 0, bv, nullptr, 0, 1);

    // 5. fused attention: scores + softmax + P@V, y bf16 out
    fused_attn_kernel<<<dim3(1, Tsz/128, Bsz*Hsz), 256, SM_ATT>>>(q, k, v, ybf);

    // 6. stylization front: hbf = silu(LN(y)*(1+scale)+shift) in bf16
    styl_kernel<<<Bsz * Tsz, 256>>>(ybf, sln_g, sln_b, embo, hbf);

    // 7. out = x + hbf @ Wout + bout  (fp32 out)
    mma_gemm3<true,true,false><<<dim3(Dsz/128, (Bsz*Tsz)/128, 1), 256, SMG128>>>(
        Dsz, hbf, Dsz, 0, 0, woutt, Dsz, 0, 0,
        out, Dsz, 0, 0, bout, x, Dsz, 1);
}